// round 3
// baseline (speedup 1.0000x reference)
#include <cuda_runtime.h>
#include <math.h>

#define BATCH 8
#define SEQ   2048
#define HID   512
#define LAYERS 8
#define MODES 32
#define KBITS 256
#define ROWS  (BATCH*SEQ)   // 16384

// ---------------- scratch (static device globals; no allocation) ----------------
__device__ float d_h [ROWS*HID];          // activations [b*S+s][h]
__device__ float d_y [ROWS*HID];          // fourier + conv pre-LN
__device__ float d_Xr[BATCH*MODES*HID];
__device__ float d_Xi[BATCH*MODES*HID];
__device__ float d_Yr[BATCH*MODES*HID];
__device__ float d_Yi[BATCH*MODES*HID];
__device__ float d_ctT[SEQ*MODES];        // cos, [s][k]
__device__ float d_stT[SEQ*MODES];        // sin, [s][k]
__device__ float d_cA [SEQ*MODES];        // irfft coef for Yr
__device__ float d_cB [SEQ*MODES];        // irfft coef for Yi
__device__ float d_o1[ROWS*(HID/2)];
__device__ float d_o2[ROWS*(HID/4)];
__device__ float d_gf[BATCH*HID];
__device__ float d_k1[BATCH*HID];

__device__ __forceinline__ float gelu_f(float x) {
    return 0.5f * x * (1.0f + erff(x * 0.7071067811865476f));
}

// ---------------- trig tables ----------------
__global__ void trig_kernel() {
    int i = blockIdx.x * blockDim.x + threadIdx.x;
    if (i >= SEQ * MODES) return;
    int s = i / MODES, k = i % MODES;
    int prod = (k * s) & (SEQ - 1);
    float ang = (float)((2.0 * 3.14159265358979323846 / (double)SEQ) * (double)prod);
    float c, sn;
    sincosf(ang, &sn, &c);   // FIXED: sincosf writes SIN to first ptr, COS to second
    d_ctT[i] = c;
    d_stT[i] = sn;
    float ck = (k == 0) ? 1.0f : 2.0f;
    d_cA[i] =  ck * c  * (1.0f / SEQ);
    d_cB[i] = -ck * sn * (1.0f / SEQ);
}

// ---------------- input projection ----------------
__global__ void inproj_kernel(const float* __restrict__ x,
                              const float* __restrict__ in_w,
                              const float* __restrict__ in_b) {
    int i = blockIdx.x * blockDim.x + threadIdx.x;  // ROWS*HID
    int bs = i >> 9, hh = i & (HID - 1);
    d_h[i] = x[bs] * in_w[hh] + in_b[hh];
}

__global__ void zeroX_kernel() {
    int i = blockIdx.x * blockDim.x + threadIdx.x;
    if (i < BATCH * MODES * HID) { d_Xr[i] = 0.0f; d_Xi[i] = 0.0f; }
}

// ---------------- truncated DFT: Xr/Xi[b,k,h] = sum_s h[b,s,h] * (cos,-sin) ----------------
__global__ void __launch_bounds__(512) dft_kernel() {
    const int b = blockIdx.x, c = blockIdx.y;  // c: 16 chunks of 128 s
    const int tid = threadIdx.x;               // h channel
    __shared__ float sc[128][MODES];
    __shared__ float ss[128][MODES];
    const int s0 = c * 128;
    for (int i = tid; i < 128 * MODES; i += 512) {
        ((float*)sc)[i] = d_ctT[s0 * MODES + i];
        ((float*)ss)[i] = d_stT[s0 * MODES + i];
    }
    __syncthreads();
    float ar[MODES], ai[MODES];
#pragma unroll
    for (int k = 0; k < MODES; k++) { ar[k] = 0.0f; ai[k] = 0.0f; }
    const float* hp = d_h + ((size_t)(b * SEQ + s0)) * HID + tid;
    for (int s = 0; s < 128; s++) {
        float v = hp[(size_t)s * HID];
#pragma unroll
        for (int k = 0; k < MODES; k += 4) {
            float4 c4 = *(const float4*)&sc[s][k];
            float4 s4 = *(const float4*)&ss[s][k];
            ar[k]   += v * c4.x;  ai[k]   -= v * s4.x;
            ar[k+1] += v * c4.y;  ai[k+1] -= v * s4.y;
            ar[k+2] += v * c4.z;  ai[k+2] -= v * s4.z;
            ar[k+3] += v * c4.w;  ai[k+3] -= v * s4.w;
        }
    }
    float* xr = d_Xr + (size_t)b * MODES * HID + tid;
    float* xi = d_Xi + (size_t)b * MODES * HID + tid;
#pragma unroll
    for (int k = 0; k < MODES; k++) {
        atomicAdd(xr + (size_t)k * HID, ar[k]);
        atomicAdd(xi + (size_t)k * HID, ai[k]);
    }
}

// ---------------- per-mode complex mix: Y[b,k,:] = X[b,k,:] @ Wc[k] ----------------
__global__ void __launch_bounds__(512) mix_kernel(const float* __restrict__ fw_r,
                                                  const float* __restrict__ fw_i,
                                                  int l) {
    const int k  = blockIdx.x;        // mode
    const int nq = blockIdx.y;        // 4 chunks of 128 out-cols
    const int tid = threadIdx.x;
    const int bb  = tid >> 6;         // batch 0..7
    const int koq = tid & 63;         // out-col pair
    __shared__ float sxr[BATCH][HID];
    __shared__ float sxi[BATCH][HID];
    for (int i = tid; i < BATCH * HID; i += 512) {
        int ib = i >> 9, ih = i & (HID - 1);
        sxr[ib][ih] = d_Xr[((size_t)ib * MODES + k) * HID + ih];
        sxi[ib][ih] = d_Xi[((size_t)ib * MODES + k) * HID + ih];
    }
    __syncthreads();
    const int ko = nq * 128 + koq * 2;
    const float* wr_p = fw_r + ((size_t)(l * MODES + k) * HID) * HID + ko;
    const float* wi_p = fw_i + ((size_t)(l * MODES + k) * HID) * HID + ko;
    float yr0 = 0, yr1 = 0, yi0 = 0, yi1 = 0;
    for (int hh = 0; hh < HID; hh++) {
        float2 wr = *(const float2*)&wr_p[(size_t)hh * HID];
        float2 wi = *(const float2*)&wi_p[(size_t)hh * HID];
        float xr = sxr[bb][hh], xi = sxi[bb][hh];
        yr0 += xr * wr.x - xi * wi.x;  yi0 += xr * wi.x + xi * wr.x;
        yr1 += xr * wr.y - xi * wi.y;  yi1 += xr * wi.y + xi * wr.y;
    }
    size_t o = ((size_t)bb * MODES + k) * HID + ko;
    d_Yr[o] = yr0; d_Yr[o + 1] = yr1;
    d_Yi[o] = yi0; d_Yi[o + 1] = yi1;
}

// ---------------- truncated inverse DFT -> d_y ----------------
__global__ void __launch_bounds__(512) idft_kernel() {
    const int b = blockIdx.x, c = blockIdx.y;
    const int tid = threadIdx.x;
    __shared__ float sA[128][MODES];
    __shared__ float sB[128][MODES];
    const int s0 = c * 128;
    for (int i = tid; i < 128 * MODES; i += 512) {
        ((float*)sA)[i] = d_cA[s0 * MODES + i];
        ((float*)sB)[i] = d_cB[s0 * MODES + i];
    }
    __syncthreads();
    float yr[MODES], yi[MODES];
#pragma unroll
    for (int k = 0; k < MODES; k++) {
        yr[k] = d_Yr[((size_t)b * MODES + k) * HID + tid];
        yi[k] = d_Yi[((size_t)b * MODES + k) * HID + tid];
    }
    float* yp = d_y + ((size_t)(b * SEQ + s0)) * HID + tid;
    for (int s = 0; s < 128; s++) {
        float acc = 0.0f;
#pragma unroll
        for (int k = 0; k < MODES; k += 4) {
            float4 a4 = *(const float4*)&sA[s][k];
            float4 b4 = *(const float4*)&sB[s][k];
            acc += a4.x * yr[k]   + b4.x * yi[k];
            acc += a4.y * yr[k+1] + b4.y * yi[k+1];
            acc += a4.z * yr[k+2] + b4.z * yi[k+2];
            acc += a4.w * yr[k+3] + b4.w * yi[k+3];
        }
        yp[(size_t)s * HID] = acc;
    }
}

// ---------------- generic tiled GEMM: Out[m,n] = act(sum_k A[m,k]*W[n,k] + bias[n] (+Src)) ----------------
template<int ACT, bool ADDSRC>
__global__ void __launch_bounds__(256) gemm_kernel(
    const float* __restrict__ A, const float* __restrict__ W,
    const float* __restrict__ bias, const float* Src,
    float* Out, int M, int N, int K)
{
    __shared__ float As[16][132];
    __shared__ float Bs[16][132];
    const int tid = threadIdx.x;
    const int m0 = blockIdx.x * 128;
    const int n0 = blockIdx.y * 128;
    const int tx = tid & 15, ty = tid >> 4;
    const int la_r = tid >> 2;          // 0..63
    const int la_k = (tid & 3) << 2;    // 0,4,8,12
    float acc[8][8];
#pragma unroll
    for (int i = 0; i < 8; i++)
#pragma unroll
        for (int j = 0; j < 8; j++) acc[i][j] = 0.0f;

    for (int k0 = 0; k0 < K; k0 += 16) {
#pragma unroll
        for (int r = 0; r < 2; r++) {
            int mm = la_r + r * 64;
            float4 va = *(const float4*)&A[(size_t)(m0 + mm) * K + k0 + la_k];
            As[la_k    ][mm] = va.x; As[la_k + 1][mm] = va.y;
            As[la_k + 2][mm] = va.z; As[la_k + 3][mm] = va.w;
            float4 vb = *(const float4*)&W[(size_t)(n0 + mm) * K + k0 + la_k];
            Bs[la_k    ][mm] = vb.x; Bs[la_k + 1][mm] = vb.y;
            Bs[la_k + 2][mm] = vb.z; Bs[la_k + 3][mm] = vb.w;
        }
        __syncthreads();
#pragma unroll
        for (int kk = 0; kk < 16; kk++) {
            float a[8], b[8];
            *(float4*)&a[0] = *(const float4*)&As[kk][ty * 8];
            *(float4*)&a[4] = *(const float4*)&As[kk][ty * 8 + 4];
            *(float4*)&b[0] = *(const float4*)&Bs[kk][tx * 8];
            *(float4*)&b[4] = *(const float4*)&Bs[kk][tx * 8 + 4];
#pragma unroll
            for (int i = 0; i < 8; i++)
#pragma unroll
                for (int j = 0; j < 8; j++)
                    acc[i][j] += a[i] * b[j];
        }
        __syncthreads();
    }
#pragma unroll
    for (int i = 0; i < 8; i++) {
        int m = m0 + ty * 8 + i;
        size_t o = (size_t)m * N + n0 + tx * 8;
#pragma unroll
        for (int j = 0; j < 8; j++) {
            float v = acc[i][j] + bias[n0 + tx * 8 + j];
            if (ADDSRC) v += Src[o + j];
            if (ACT == 1) v = gelu_f(v);
            Out[o + j] = v;
        }
    }
}

// ---------------- layernorm + residual: d_h = LN(d_y)*g + b + d_h ----------------
__global__ void __launch_bounds__(512) ln_kernel(const float* __restrict__ g,
                                                 const float* __restrict__ bta) {
    const int row = blockIdx.x;
    const int tid = threadIdx.x;
    __shared__ float sred[16];
    const int lane = tid & 31, w = tid >> 5;
    float v = d_y[(size_t)row * HID + tid];

    float s = v;
#pragma unroll
    for (int o = 16; o > 0; o >>= 1) s += __shfl_down_sync(0xffffffffu, s, o);
    if (lane == 0) sred[w] = s;
    __syncthreads();
    if (w == 0) {
        float t = (lane < 16) ? sred[lane] : 0.0f;
#pragma unroll
        for (int o = 8; o > 0; o >>= 1) t += __shfl_down_sync(0xffffffffu, t, o);
        if (lane == 0) sred[0] = t;
    }
    __syncthreads();
    float mu = sred[0] * (1.0f / HID);
    __syncthreads();

    float d = v - mu;
    float s2 = d * d;
#pragma unroll
    for (int o = 16; o > 0; o >>= 1) s2 += __shfl_down_sync(0xffffffffu, s2, o);
    if (lane == 0) sred[w] = s2;
    __syncthreads();
    if (w == 0) {
        float t = (lane < 16) ? sred[lane] : 0.0f;
#pragma unroll
        for (int o = 8; o > 0; o >>= 1) t += __shfl_down_sync(0xffffffffu, t, o);
        if (lane == 0) sred[0] = t;
    }
    __syncthreads();
    float var = sred[0] * (1.0f / HID);
    float r = rsqrtf(var + 1e-5f);

    size_t idx = (size_t)row * HID + tid;
    d_h[idx] = d * r * g[tid] + bta[tid] + d_h[idx];
}

// ---------------- final scalar projection: out[row] = o2[row,:] . w + b ----------------
__global__ void op3_kernel(const float* __restrict__ w, const float* __restrict__ b3,
                           float* __restrict__ out) {
    int row = blockIdx.x * 8 + (threadIdx.x >> 5);
    int lane = threadIdx.x & 31;
    const float* o2 = d_o2 + (size_t)row * (HID / 4);
    float s = 0.0f;
#pragma unroll
    for (int i = 0; i < 4; i++) s += o2[lane + i * 32] * w[lane + i * 32];
#pragma unroll
    for (int o = 16; o > 0; o >>= 1) s += __shfl_down_sync(0xffffffffu, s, o);
    if (lane == 0) out[row] = s + b3[0];
}

// ---------------- global feature mean over S ----------------
__global__ void zerogf_kernel() {
    int i = blockIdx.x * blockDim.x + threadIdx.x;
    if (i < BATCH * HID) d_gf[i] = 0.0f;
}
__global__ void __launch_bounds__(512) gf_kernel() {
    const int b = blockIdx.x, c = blockIdx.y;
    const int tid = threadIdx.x;
    const float* hp = d_h + ((size_t)(b * SEQ + c * 128)) * HID + tid;
    float acc = 0.0f;
    for (int s = 0; s < 128; s++) acc += hp[(size_t)s * HID];
    atomicAdd(&d_gf[b * HID + tid], acc * (1.0f / SEQ));
}

// ---------------- crypt head ----------------
__global__ void __launch_bounds__(512) head1_kernel(const float* __restrict__ w,
                                                    const float* __restrict__ bias) {
    const int b = blockIdx.x, t = threadIdx.x;
    __shared__ float sg[HID];
    sg[t] = d_gf[b * HID + t];
    __syncthreads();
    float acc = bias[t];
    const float* wr = w + (size_t)t * HID;
    for (int hh = 0; hh < HID; hh += 4) {
        float4 w4 = *(const float4*)&wr[hh];
        acc += sg[hh] * w4.x + sg[hh+1] * w4.y + sg[hh+2] * w4.z + sg[hh+3] * w4.w;
    }
    d_k1[b * HID + t] = gelu_f(acc);
}
__global__ void __launch_bounds__(256) head2_kernel(const float* __restrict__ w,
                                                    const float* __restrict__ bias,
                                                    float* __restrict__ out) {
    const int b = blockIdx.x, t = threadIdx.x;
    __shared__ float sk[HID];
    sk[t] = d_k1[b * HID + t];
    sk[t + 256] = d_k1[b * HID + t + 256];
    __syncthreads();
    float acc = bias[t];
    const float* wr = w + (size_t)t * HID;
    for (int hh = 0; hh < HID; hh += 4) {
        float4 w4 = *(const float4*)&wr[hh];
        acc += sk[hh] * w4.x + sk[hh+1] * w4.y + sk[hh+2] * w4.z + sk[hh+3] * w4.w;
    }
    out[ROWS + b * KBITS + t] = 1.0f / (1.0f + expf(-acc));
}

// ---------------- launch ----------------
extern "C" void kernel_launch(void* const* d_in, const int* in_sizes, int n_in,
                              void* d_out, int out_size) {
    const float* x      = (const float*)d_in[0];
    const float* in_w   = (const float*)d_in[1];
    const float* in_b   = (const float*)d_in[2];
    const float* fw_r   = (const float*)d_in[3];
    const float* fw_i   = (const float*)d_in[4];
    const float* conv_w = (const float*)d_in[5];
    const float* conv_b = (const float*)d_in[6];
    const float* ln_g   = (const float*)d_in[7];
    const float* ln_b   = (const float*)d_in[8];
    const float* op1_w  = (const float*)d_in[9];
    const float* op1_b  = (const float*)d_in[10];
    const float* op2_w  = (const float*)d_in[11];
    const float* op2_b  = (const float*)d_in[12];
    const float* op3_w  = (const float*)d_in[13];
    const float* op3_b  = (const float*)d_in[14];
    const float* h1_w   = (const float*)d_in[15];
    const float* h1_b   = (const float*)d_in[16];
    const float* h2_w   = (const float*)d_in[17];
    const float* h2_b   = (const float*)d_in[18];
    float* out = (float*)d_out;

    void* p;
    cudaGetSymbolAddress(&p, d_h);   float* ph  = (float*)p;
    cudaGetSymbolAddress(&p, d_y);   float* py  = (float*)p;
    cudaGetSymbolAddress(&p, d_o1);  float* po1 = (float*)p;
    cudaGetSymbolAddress(&p, d_o2);  float* po2 = (float*)p;

    trig_kernel<<<(SEQ * MODES + 255) / 256, 256>>>();
    inproj_kernel<<<(ROWS * HID) / 256, 256>>>(x, in_w, in_b);

    for (int l = 0; l < LAYERS; l++) {
        zeroX_kernel<<<(BATCH * MODES * HID + 255) / 256, 256>>>();
        dft_kernel<<<dim3(BATCH, 16), 512>>>();
        mix_kernel<<<dim3(MODES, 4), 512>>>(fw_r, fw_i, l);
        idft_kernel<<<dim3(BATCH, 16), 512>>>();
        // conv: d_y = fourier(d_y) + d_h @ conv_w[l]^T + conv_b[l]
        gemm_kernel<0, true><<<dim3(ROWS / 128, HID / 128), 256>>>(
            ph, conv_w + (size_t)l * HID * HID, conv_b + l * HID, py, py, ROWS, HID, HID);
        ln_kernel<<<ROWS, 512>>>(ln_g + l * HID, ln_b + l * HID);
    }

    gemm_kernel<1, false><<<dim3(ROWS / 128, (HID / 2) / 128), 256>>>(
        ph, op1_w, op1_b, (const float*)0, po1, ROWS, HID / 2, HID);
    gemm_kernel<1, false><<<dim3(ROWS / 128, (HID / 4) / 128), 256>>>(
        po1, op2_w, op2_b, (const float*)0, po2, ROWS, HID / 4, HID / 2);
    op3_kernel<<<ROWS / 8, 256>>>(op3_w, op3_b, out);

    zerogf_kernel<<<(BATCH * HID + 255) / 256, 256>>>();
    gf_kernel<<<dim3(BATCH, 16), 512>>>();
    head1_kernel<<<BATCH, 512>>>(h1_w, h1_b);
    head2_kernel<<<BATCH, 256>>>(h2_w, h2_b, out);
}

// round 5
// speedup vs baseline: 1.1222x; 1.1222x over previous
#include <cuda_runtime.h>
#include <cuda_bf16.h>
#include <math.h>
#include <stdint.h>

#define BATCH 8
#define SEQ   2048
#define HID   512
#define LAYERS 8
#define MODES 32
#define KBITS 256
#define ROWS  (BATCH*SEQ)   // 16384

// ---------------- scratch (static device globals; no allocation) ----------------
__device__ __align__(16) float d_h [ROWS*HID];
__device__ __align__(16) float d_y [ROWS*HID];
__device__ __align__(16) float d_Xr[BATCH*MODES*HID];
__device__ __align__(16) float d_Xi[BATCH*MODES*HID];
__device__ __align__(16) float d_Yr[BATCH*MODES*HID];
__device__ __align__(16) float d_Yi[BATCH*MODES*HID];
__device__ __align__(16) float d_ctT[SEQ*MODES];
__device__ __align__(16) float d_stT[SEQ*MODES];
__device__ __align__(16) float d_cA [SEQ*MODES];
__device__ __align__(16) float d_cB [SEQ*MODES];
__device__ __align__(16) float d_o1[ROWS*(HID/2)];
__device__ __align__(16) float d_o2[ROWS*(HID/4)];
__device__ __align__(16) float d_gf[BATCH*HID];
__device__ __align__(16) float d_k1[BATCH*HID];

// bf16 split buffers (A' = [hi|hi|lo], W' = [hi|lo|hi] over K'=3K)
__device__ __align__(16) __nv_bfloat16 d_A3[ROWS*3*HID];                 // 16384 x 1536
__device__ __align__(16) __nv_bfloat16 d_W3conv[LAYERS*HID*3*HID];       // (8*512) x 1536
__device__ __align__(16) __nv_bfloat16 d_W3op1[(HID/2)*3*HID];           // 256 x 1536
__device__ __align__(16) __nv_bfloat16 d_W3op2[(HID/4)*3*(HID/2)];       // 128 x 768

__device__ __forceinline__ float gelu_f(float x) {
    return 0.5f * x * (1.0f + erff(x * 0.7071067811865476f));
}

// ---------------- trig tables ----------------
__global__ void trig_kernel() {
    int i = blockIdx.x * blockDim.x + threadIdx.x;
    if (i >= SEQ * MODES) return;
    int s = i / MODES, k = i % MODES;
    int prod = (k * s) & (SEQ - 1);
    float ang = (float)((2.0 * 3.14159265358979323846 / (double)SEQ) * (double)prod);
    float c, sn;
    sincosf(ang, &sn, &c);   // sincosf writes SIN first, COS second
    d_ctT[i] = c;
    d_stT[i] = sn;
    float ck = (k == 0) ? 1.0f : 2.0f;
    d_cA[i] =  ck * c  * (1.0f / SEQ);
    d_cB[i] = -ck * sn * (1.0f / SEQ);
}

// ---------------- input projection ----------------
__global__ void inproj_kernel(const float* __restrict__ x,
                              const float* __restrict__ in_w,
                              const float* __restrict__ in_b) {
    int i = blockIdx.x * blockDim.x + threadIdx.x;
    int bs = i >> 9, hh = i & (HID - 1);
    d_h[i] = x[bs] * in_w[hh] + in_b[hh];
}

__global__ void zeroX_kernel() {
    int i = blockIdx.x * blockDim.x + threadIdx.x;
    if (i < BATCH * MODES * HID) { d_Xr[i] = 0.0f; d_Xi[i] = 0.0f; }
}

// ---------------- bf16 two-term split ----------------
// MODE 0 (activations): blocks [hi | hi | lo];  MODE 1 (weights): [hi | lo | hi]
template<int MODE>
__global__ void split_kernel(const float* __restrict__ X, __nv_bfloat16* __restrict__ O,
                             int total, int K) {
    int i = blockIdx.x * blockDim.x + threadIdx.x;
    if (i >= total) return;
    int r = i / K, k = i - r * K;
    float v = X[i];
    __nv_bfloat16 hi = __float2bfloat16(v);
    float lo = v - __bfloat162float(hi);
    __nv_bfloat16 lob = __float2bfloat16(lo);
    size_t base = (size_t)r * (3 * K);
    if (MODE == 0) {
        O[base + k] = hi; O[base + K + k] = hi; O[base + 2 * K + k] = lob;
    } else {
        O[base + k] = hi; O[base + K + k] = lob; O[base + 2 * K + k] = hi;
    }
}

// ---------------- truncated DFT ----------------
__global__ void __launch_bounds__(512) dft_kernel() {
    const int b = blockIdx.x, c = blockIdx.y;
    const int tid = threadIdx.x;
    __shared__ float sc[128][MODES];
    __shared__ float ss[128][MODES];
    const int s0 = c * 128;
    for (int i = tid; i < 128 * MODES; i += 512) {
        ((float*)sc)[i] = d_ctT[s0 * MODES + i];
        ((float*)ss)[i] = d_stT[s0 * MODES + i];
    }
    __syncthreads();
    float ar[MODES], ai[MODES];
#pragma unroll
    for (int k = 0; k < MODES; k++) { ar[k] = 0.0f; ai[k] = 0.0f; }
    const float* hp = d_h + ((size_t)(b * SEQ + s0)) * HID + tid;
    for (int s = 0; s < 128; s++) {
        float v = hp[(size_t)s * HID];
#pragma unroll
        for (int k = 0; k < MODES; k += 4) {
            float4 c4 = *(const float4*)&sc[s][k];
            float4 s4 = *(const float4*)&ss[s][k];
            ar[k]   += v * c4.x;  ai[k]   -= v * s4.x;
            ar[k+1] += v * c4.y;  ai[k+1] -= v * s4.y;
            ar[k+2] += v * c4.z;  ai[k+2] -= v * s4.z;
            ar[k+3] += v * c4.w;  ai[k+3] -= v * s4.w;
        }
    }
    float* xr = d_Xr + (size_t)b * MODES * HID + tid;
    float* xi = d_Xi + (size_t)b * MODES * HID + tid;
#pragma unroll
    for (int k = 0; k < MODES; k++) {
        atomicAdd(xr + (size_t)k * HID, ar[k]);
        atomicAdd(xi + (size_t)k * HID, ai[k]);
    }
}

// ---------------- per-mode complex mix ----------------
__global__ void __launch_bounds__(512) mix_kernel(const float* __restrict__ fw_r,
                                                  const float* __restrict__ fw_i,
                                                  int l) {
    const int k  = blockIdx.x;
    const int nq = blockIdx.y;
    const int tid = threadIdx.x;
    const int bb  = tid >> 6;
    const int koq = tid & 63;
    __shared__ float sxr[BATCH][HID];
    __shared__ float sxi[BATCH][HID];
    for (int i = tid; i < BATCH * HID; i += 512) {
        int ib = i >> 9, ih = i & (HID - 1);
        sxr[ib][ih] = d_Xr[((size_t)ib * MODES + k) * HID + ih];
        sxi[ib][ih] = d_Xi[((size_t)ib * MODES + k) * HID + ih];
    }
    __syncthreads();
    const int ko = nq * 128 + koq * 2;
    const float* wr_p = fw_r + ((size_t)(l * MODES + k) * HID) * HID + ko;
    const float* wi_p = fw_i + ((size_t)(l * MODES + k) * HID) * HID + ko;
    float yr0 = 0, yr1 = 0, yi0 = 0, yi1 = 0;
    for (int hh = 0; hh < HID; hh++) {
        float2 wr = *(const float2*)&wr_p[(size_t)hh * HID];
        float2 wi = *(const float2*)&wi_p[(size_t)hh * HID];
        float xr = sxr[bb][hh], xi = sxi[bb][hh];
        yr0 += xr * wr.x - xi * wi.x;  yi0 += xr * wi.x + xi * wr.x;
        yr1 += xr * wr.y - xi * wi.y;  yi1 += xr * wi.y + xi * wr.y;
    }
    size_t o = ((size_t)bb * MODES + k) * HID + ko;
    d_Yr[o] = yr0; d_Yr[o + 1] = yr1;
    d_Yi[o] = yi0; d_Yi[o + 1] = yi1;
}

// ---------------- truncated inverse DFT ----------------
__global__ void __launch_bounds__(512) idft_kernel() {
    const int b = blockIdx.x, c = blockIdx.y;
    const int tid = threadIdx.x;
    __shared__ float sA[128][MODES];
    __shared__ float sB[128][MODES];
    const int s0 = c * 128;
    for (int i = tid; i < 128 * MODES; i += 512) {
        ((float*)sA)[i] = d_cA[s0 * MODES + i];
        ((float*)sB)[i] = d_cB[s0 * MODES + i];
    }
    __syncthreads();
    float yr[MODES], yi[MODES];
#pragma unroll
    for (int k = 0; k < MODES; k++) {
        yr[k] = d_Yr[((size_t)b * MODES + k) * HID + tid];
        yi[k] = d_Yi[((size_t)b * MODES + k) * HID + tid];
    }
    float* yp = d_y + ((size_t)(b * SEQ + s0)) * HID + tid;
    for (int s = 0; s < 128; s++) {
        float acc = 0.0f;
#pragma unroll
        for (int k = 0; k < MODES; k += 4) {
            float4 a4 = *(const float4*)&sA[s][k];
            float4 b4 = *(const float4*)&sB[s][k];
            acc += a4.x * yr[k]   + b4.x * yi[k];
            acc += a4.y * yr[k+1] + b4.y * yi[k+1];
            acc += a4.z * yr[k+2] + b4.z * yi[k+2];
            acc += a4.w * yr[k+3] + b4.w * yi[k+3];
        }
        yp[(size_t)s * HID] = acc;
    }
}

// ---------------- tensor-core bf16 GEMM ----------------
// Out[m,n] = act( sum_k A[m,k]*W[n,k] + bias[n] (+Src) )
// A: [M][Kp] bf16 row-major, W: [N][Kp] bf16 row-major. BM=BN=128, BK=32.
__device__ __forceinline__ void ldmat_x4(uint32_t* r, const __nv_bfloat16* p) {
    uint32_t a = (uint32_t)__cvta_generic_to_shared(p);
    asm volatile("ldmatrix.sync.aligned.m8n8.x4.shared.b16 {%0,%1,%2,%3}, [%4];"
                 : "=r"(r[0]), "=r"(r[1]), "=r"(r[2]), "=r"(r[3]) : "r"(a));
}
__device__ __forceinline__ void ldmat_x2(uint32_t* r, const __nv_bfloat16* p) {
    uint32_t a = (uint32_t)__cvta_generic_to_shared(p);
    asm volatile("ldmatrix.sync.aligned.m8n8.x2.shared.b16 {%0,%1}, [%2];"
                 : "=r"(r[0]), "=r"(r[1]) : "r"(a));
}
__device__ __forceinline__ void mma16816(float* c, const uint32_t* a, const uint32_t* b) {
    asm volatile("mma.sync.aligned.m16n8k16.row.col.f32.bf16.bf16.f32 "
                 "{%0,%1,%2,%3}, {%4,%5,%6,%7}, {%8,%9}, {%0,%1,%2,%3};"
                 : "+f"(c[0]), "+f"(c[1]), "+f"(c[2]), "+f"(c[3])
                 : "r"(a[0]), "r"(a[1]), "r"(a[2]), "r"(a[3]), "r"(b[0]), "r"(b[1]));
}

template<int ACT, bool ADDSRC>
__global__ void __launch_bounds__(256) gemm_bf16_kernel(
    const __nv_bfloat16* __restrict__ A, const __nv_bfloat16* __restrict__ W,
    const float* __restrict__ bias, const float* __restrict__ Src,
    float* __restrict__ Out, int M, int N, int Kp)
{
    __shared__ __nv_bfloat16 sA[2][128][40];
    __shared__ __nv_bfloat16 sB[2][128][40];
    const int tid  = threadIdx.x;
    const int m0   = blockIdx.x * 128;
    const int n0   = blockIdx.y * 128;
    const int lrow = tid >> 1;
    const int lcol = (tid & 1) * 16;
    const int lane = tid & 31;
    const int wid  = tid >> 5;
    const int wm   = wid & 1;   // 0..1 : 64-row band
    const int wn   = wid >> 1;  // 0..3 : 32-col band

    float c[4][4][4];
#pragma unroll
    for (int mt = 0; mt < 4; mt++)
#pragma unroll
        for (int nt = 0; nt < 4; nt++)
#pragma unroll
            for (int q = 0; q < 4; q++) c[mt][nt][q] = 0.0f;

    const int nk = Kp >> 5;
    const __nv_bfloat16* Ap = A + (size_t)(m0 + lrow) * Kp + lcol;
    const __nv_bfloat16* Bp = W + (size_t)(n0 + lrow) * Kp + lcol;

    uint4 ra0 = *(const uint4*)Ap;
    uint4 ra1 = *(const uint4*)(Ap + 8);
    uint4 rb0 = *(const uint4*)Bp;
    uint4 rb1 = *(const uint4*)(Bp + 8);
    *(uint4*)&sA[0][lrow][lcol]     = ra0;
    *(uint4*)&sA[0][lrow][lcol + 8] = ra1;
    *(uint4*)&sB[0][lrow][lcol]     = rb0;
    *(uint4*)&sB[0][lrow][lcol + 8] = rb1;
    __syncthreads();

    // ldmatrix lane address components
    const int a_r = lane & 15;           // row within 16
    const int a_c = (lane >> 4) << 3;    // 0 or 8
    const int b_r = lane & 7;
    const int b_c = ((lane >> 3) & 1) << 3;

    int buf = 0;
    for (int kt = 0; kt < nk; kt++) {
        if (kt + 1 < nk) {
            const __nv_bfloat16* Ap2 = Ap + (size_t)(kt + 1) * 32;
            const __nv_bfloat16* Bp2 = Bp + (size_t)(kt + 1) * 32;
            ra0 = *(const uint4*)Ap2; ra1 = *(const uint4*)(Ap2 + 8);
            rb0 = *(const uint4*)Bp2; rb1 = *(const uint4*)(Bp2 + 8);
        }
#pragma unroll
        for (int ks = 0; ks < 32; ks += 16) {
            uint32_t af[4][4], bf[4][2];
#pragma unroll
            for (int mt = 0; mt < 4; mt++)
                ldmat_x4(af[mt], &sA[buf][wm * 64 + mt * 16 + a_r][ks + a_c]);
#pragma unroll
            for (int nt = 0; nt < 4; nt++)
                ldmat_x2(bf[nt], &sB[buf][wn * 32 + nt * 8 + b_r][ks + b_c]);
#pragma unroll
            for (int mt = 0; mt < 4; mt++)
#pragma unroll
                for (int nt = 0; nt < 4; nt++)
                    mma16816(c[mt][nt], af[mt], bf[nt]);
        }
        if (kt + 1 < nk) {
            *(uint4*)&sA[buf ^ 1][lrow][lcol]     = ra0;
            *(uint4*)&sA[buf ^ 1][lrow][lcol + 8] = ra1;
            *(uint4*)&sB[buf ^ 1][lrow][lcol]     = rb0;
            *(uint4*)&sB[buf ^ 1][lrow][lcol + 8] = rb1;
        }
        __syncthreads();
        buf ^= 1;
    }

#pragma unroll
    for (int mt = 0; mt < 4; mt++) {
        int m = m0 + wm * 64 + mt * 16 + (lane >> 2);
#pragma unroll
        for (int nt = 0; nt < 4; nt++) {
            int n = n0 + wn * 32 + nt * 8 + ((lane & 3) << 1);
            float bn0 = bias[n], bn1 = bias[n + 1];
            size_t o0 = (size_t)m * N + n;
            size_t o1 = (size_t)(m + 8) * N + n;
            float v0 = c[mt][nt][0] + bn0, v1 = c[mt][nt][1] + bn1;
            float v2 = c[mt][nt][2] + bn0, v3 = c[mt][nt][3] + bn1;
            if (ADDSRC) {
                v0 += Src[o0]; v1 += Src[o0 + 1];
                v2 += Src[o1]; v3 += Src[o1 + 1];
            }
            if (ACT == 1) { v0 = gelu_f(v0); v1 = gelu_f(v1); v2 = gelu_f(v2); v3 = gelu_f(v3); }
            float2 w0 = {v0, v1}, w1 = {v2, v3};
            *(float2*)&Out[o0] = w0;
            *(float2*)&Out[o1] = w1;
        }
    }
}

// ---------------- layernorm + residual: d_h = LN(d_y)*g + b + d_h ----------------
__global__ void __launch_bounds__(512) ln_kernel(const float* __restrict__ g,
                                                 const float* __restrict__ bta) {
    const int row = blockIdx.x;
    const int tid = threadIdx.x;
    __shared__ float sred[16];
    const int lane = tid & 31, w = tid >> 5;
    float v = d_y[(size_t)row * HID + tid];

    float s = v;
#pragma unroll
    for (int o = 16; o > 0; o >>= 1) s += __shfl_down_sync(0xffffffffu, s, o);
    if (lane == 0) sred[w] = s;
    __syncthreads();
    if (w == 0) {
        float t = (lane < 16) ? sred[lane] : 0.0f;
#pragma unroll
        for (int o = 8; o > 0; o >>= 1) t += __shfl_down_sync(0xffffffffu, t, o);
        if (lane == 0) sred[0] = t;
    }
    __syncthreads();
    float mu = sred[0] * (1.0f / HID);
    __syncthreads();

    float d = v - mu;
    float s2 = d * d;
#pragma unroll
    for (int o = 16; o > 0; o >>= 1) s2 += __shfl_down_sync(0xffffffffu, s2, o);
    if (lane == 0) sred[w] = s2;
    __syncthreads();
    if (w == 0) {
        float t = (lane < 16) ? sred[lane] : 0.0f;
#pragma unroll
        for (int o = 8; o > 0; o >>= 1) t += __shfl_down_sync(0xffffffffu, t, o);
        if (lane == 0) sred[0] = t;
    }
    __syncthreads();
    float var = sred[0] * (1.0f / HID);
    float r = rsqrtf(var + 1e-5f);

    size_t idx = (size_t)row * HID + tid;
    d_h[idx] = d * r * g[tid] + bta[tid] + d_h[idx];
}

// ---------------- final scalar projection ----------------
__global__ void op3_kernel(const float* __restrict__ w, const float* __restrict__ b3,
                           float* __restrict__ out) {
    int row = blockIdx.x * 8 + (threadIdx.x >> 5);
    int lane = threadIdx.x & 31;
    const float* o2 = d_o2 + (size_t)row * (HID / 4);
    float s = 0.0f;
#pragma unroll
    for (int i = 0; i < 4; i++) s += o2[lane + i * 32] * w[lane + i * 32];
#pragma unroll
    for (int o = 16; o > 0; o >>= 1) s += __shfl_down_sync(0xffffffffu, s, o);
    if (lane == 0) out[row] = s + b3[0];
}

// ---------------- global feature mean ----------------
__global__ void zerogf_kernel() {
    int i = blockIdx.x * blockDim.x + threadIdx.x;
    if (i < BATCH * HID) d_gf[i] = 0.0f;
}
__global__ void __launch_bounds__(512) gf_kernel() {
    const int b = blockIdx.x, c = blockIdx.y;
    const int tid = threadIdx.x;
    const float* hp = d_h + ((size_t)(b * SEQ + c * 128)) * HID + tid;
    float acc = 0.0f;
    for (int s = 0; s < 128; s++) acc += hp[(size_t)s * HID];
    atomicAdd(&d_gf[b * HID + tid], acc * (1.0f / SEQ));
}

// ---------------- crypt head ----------------
__global__ void __launch_bounds__(512) head1_kernel(const float* __restrict__ w,
                                                    const float* __restrict__ bias) {
    const int b = blockIdx.x, t = threadIdx.x;
    __shared__ float sg[HID];
    sg[t] = d_gf[b * HID + t];
    __syncthreads();
    float acc = bias[t];
    const float* wr = w + (size_t)t * HID;
    for (int hh = 0; hh < HID; hh += 4) {
        float4 w4 = *(const float4*)&wr[hh];
        acc += sg[hh] * w4.x + sg[hh+1] * w4.y + sg[hh+2] * w4.z + sg[hh+3] * w4.w;
    }
    d_k1[b * HID + t] = gelu_f(acc);
}
__global__ void __launch_bounds__(256) head2_kernel(const float* __restrict__ w,
                                                    const float* __restrict__ bias,
                                                    float* __restrict__ out) {
    const int b = blockIdx.x, t = threadIdx.x;
    __shared__ float sk[HID];
    sk[t] = d_k1[b * HID + t];
    sk[t + 256] = d_k1[b * HID + t + 256];
    __syncthreads();
    float acc = bias[t];
    const float* wr = w + (size_t)t * HID;
    for (int hh = 0; hh < HID; hh += 4) {
        float4 w4 = *(const float4*)&wr[hh];
        acc += sk[hh] * w4.x + sk[hh+1] * w4.y + sk[hh+2] * w4.z + sk[hh+3] * w4.w;
    }
    out[ROWS + b * KBITS + t] = 1.0f / (1.0f + expf(-acc));
}

// ---------------- launch ----------------
extern "C" void kernel_launch(void* const* d_in, const int* in_sizes, int n_in,
                              void* d_out, int out_size) {
    const float* x      = (const float*)d_in[0];
    const float* in_w   = (const float*)d_in[1];
    const float* in_b   = (const float*)d_in[2];
    const float* fw_r   = (const float*)d_in[3];
    const float* fw_i   = (const float*)d_in[4];
    const float* conv_w = (const float*)d_in[5];
    const float* conv_b = (const float*)d_in[6];
    const float* ln_g   = (const float*)d_in[7];
    const float* ln_b   = (const float*)d_in[8];
    const float* op1_w  = (const float*)d_in[9];
    const float* op1_b  = (const float*)d_in[10];
    const float* op2_w  = (const float*)d_in[11];
    const float* op2_b  = (const float*)d_in[12];
    const float* op3_w  = (const float*)d_in[13];
    const float* op3_b  = (const float*)d_in[14];
    const float* h1_w   = (const float*)d_in[15];
    const float* h1_b   = (const float*)d_in[16];
    const float* h2_w   = (const float*)d_in[17];
    const float* h2_b   = (const float*)d_in[18];
    float* out = (float*)d_out;

    void* p;
    cudaGetSymbolAddress(&p, d_h);      float* ph  = (float*)p;
    cudaGetSymbolAddress(&p, d_y);      float* py  = (float*)p;
    cudaGetSymbolAddress(&p, d_o1);     float* po1 = (float*)p;
    cudaGetSymbolAddress(&p, d_o2);     float* po2 = (float*)p;
    cudaGetSymbolAddress(&p, d_A3);     __nv_bfloat16* pA3 = (__nv_bfloat16*)p;
    cudaGetSymbolAddress(&p, d_W3conv); __nv_bfloat16* pWc = (__nv_bfloat16*)p;
    cudaGetSymbolAddress(&p, d_W3op1);  __nv_bfloat16* pW1 = (__nv_bfloat16*)p;
    cudaGetSymbolAddress(&p, d_W3op2);  __nv_bfloat16* pW2 = (__nv_bfloat16*)p;

    trig_kernel<<<(SEQ * MODES + 255) / 256, 256>>>();
    inproj_kernel<<<(ROWS * HID) / 256, 256>>>(x, in_w, in_b);

    // split weights once per launch
    split_kernel<1><<<(LAYERS * HID * HID + 255) / 256, 256>>>(conv_w, pWc, LAYERS * HID * HID, HID);
    split_kernel<1><<<((HID / 2) * HID + 255) / 256, 256>>>(op1_w, pW1, (HID / 2) * HID, HID);
    split_kernel<1><<<((HID / 4) * (HID / 2) + 255) / 256, 256>>>(op2_w, pW2, (HID / 4) * (HID / 2), HID / 2);

    for (int l = 0; l < LAYERS; l++) {
        zeroX_kernel<<<(BATCH * MODES * HID + 255) / 256, 256>>>();
        dft_kernel<<<dim3(BATCH, 16), 512>>>();
        mix_kernel<<<dim3(MODES, 4), 512>>>(fw_r, fw_i, l);
        idft_kernel<<<dim3(BATCH, 16), 512>>>();
        split_kernel<0><<<(ROWS * HID + 255) / 256, 256>>>(ph, pA3, ROWS * HID, HID);
        gemm_bf16_kernel<0, true><<<dim3(ROWS / 128, HID / 128), 256>>>(
            pA3, pWc + (size_t)l * HID * 3 * HID, conv_b + l * HID, py, py,
            ROWS, HID, 3 * HID);
        ln_kernel<<<ROWS, 512>>>(ln_g + l * HID, ln_b + l * HID);
    }

    split_kernel<0><<<(ROWS * HID + 255) / 256, 256>>>(ph, pA3, ROWS * HID, HID);
    gemm_bf16_kernel<1, false><<<dim3(ROWS / 128, (HID / 2) / 128), 256>>>(
        pA3, pW1, op1_b, (const float*)0, po1, ROWS, HID / 2, 3 * HID);
    split_kernel<0><<<(ROWS * (HID / 2) + 255) / 256, 256>>>(po1, pA3, ROWS * (HID / 2), HID / 2);
    gemm_bf16_kernel<1, false><<<dim3(ROWS / 128, (HID / 4) / 128), 256>>>(
        pA3, pW2, op2_b, (const float*)0, po2, ROWS, HID / 4, 3 * (HID / 2));
    op3_kernel<<<ROWS / 8, 256>>>(op3_w, op3_b, out);

    zerogf_kernel<<<(BATCH * HID + 255) / 256, 256>>>();
    gf_kernel<<<dim3(BATCH, 16), 512>>>();
    head1_kernel<<<BATCH, 512>>>(h1_w, h1_b);
    head2_kernel<<<BATCH, 256>>>(h2_w, h2_b, out);
}